// round 15
// baseline (speedup 1.0000x reference)
#include <cuda_runtime.h>
#include <cstdint>

// ============================================================================
// Problem constants
// ============================================================================
static constexpr int N_ROWS = 16384;   // N nodes
static constexpr int F_DIM  = 64;      // features
static constexpr int U_DIM  = 64;      // output units

// Transposed expmap output: g_xT[n][k] = x_proj[k][n], [64, 16384] fp32 (tf32-rounded)
__device__ float g_xT[(size_t)F_DIM * N_ROWS];

// ============================================================================
// Helpers — baseline PTX only (sm_103, NO 'a'-suffix features)
// ============================================================================
__device__ __forceinline__ uint32_t smem_u32(const void* p) {
    uint32_t a;
    asm("{ .reg .u64 t; cvta.to.shared.u64 t, %1; cvt.u32.u64 %0, t; }"
        : "=r"(a) : "l"(p));
    return a;
}

// SW128 swizzle valid for 128-byte rows: XOR bits[6:4] with row&7
#define SW128(x) ((x) ^ (((x) >> 3) & 0x70))

__device__ __forceinline__ void cp_async16(uint32_t saddr, const void* gptr) {
    asm volatile("cp.async.cg.shared.global [%0], [%1], 16;"
                 :: "r"(saddr), "l"(gptr) : "memory");
}
#define CP_COMMIT() asm volatile("cp.async.commit_group;" ::: "memory")
template <int Ngrp>
__device__ __forceinline__ void cp_wait() {
    asm volatile("cp.async.wait_group %0;" :: "n"(Ngrp) : "memory");
}

__device__ __forceinline__ void ldsm_x4(uint32_t r[4], uint32_t addr) {
    asm volatile("ldmatrix.sync.aligned.m8n8.x4.shared.b16 {%0,%1,%2,%3}, [%4];"
                 : "=r"(r[0]), "=r"(r[1]), "=r"(r[2]), "=r"(r[3]) : "r"(addr));
}

__device__ __forceinline__ uint32_t cvt_rna_tf32(uint32_t x) {
    uint32_t y;
    asm("cvt.rna.tf32.f32 %0, %1;" : "=r"(y) : "f"(__uint_as_float(x)));
    return y;
}

// D += A*B, m16n8k8 tf32, fp32 accumulate (sm_80+ baseline ISA)
__device__ __forceinline__ void mma_tf32(float d[4], const uint32_t a[4],
                                         uint32_t b0, uint32_t b1) {
    asm volatile(
        "mma.sync.aligned.m16n8k8.row.col.f32.tf32.tf32.f32 "
        "{%0,%1,%2,%3}, {%4,%5,%6,%7}, {%8,%9}, {%0,%1,%2,%3};"
        : "+f"(d[0]), "+f"(d[1]), "+f"(d[2]), "+f"(d[3])
        : "r"(a[0]), "r"(a[1]), "r"(a[2]), "r"(a[3]), "r"(b0), "r"(b1));
}

// ============================================================================
// Kernel 1: Poincare expmap + transpose (x[16384,64] -> g_xT[64,16384])
// ============================================================================
__global__ __launch_bounds__(256) void expmap_transpose(const float* __restrict__ x) {
    __shared__ float tile[64][65];
    __shared__ float scl[64];
    const int k0 = blockIdx.x * 64;
    const int t = threadIdx.x;

#pragma unroll
    for (int i = 0; i < 16; i++) {
        int idx = t + i * 256;
        int r = idx >> 6, c = idx & 63;
        tile[r][c] = x[(size_t)(k0 + r) * F_DIM + c];
    }
    __syncthreads();

    if (t < 64) {
        float s = 0.0f;
#pragma unroll
        for (int c = 0; c < 64; c++) { float v = tile[t][c]; s += v * v; }
        float n = fminf(sqrtf(s), 10.0f);
        scl[t] = tanhf(n) / (n + 1e-8f);
    }
    __syncthreads();

    const int kl = t & 63;
    const int ng = t >> 6;  // 4 groups of 64 threads
#pragma unroll
    for (int nn = ng; nn < 64; nn += 4) {
        float v = tile[kl][nn] * scl[kl];
        uint32_t u;
        asm("cvt.rna.tf32.f32 %0, %1;" : "=r"(u) : "f"(v));  // pre-round B: no bias
        g_xT[(size_t)nn * N_ROWS + k0 + kl] = __uint_as_float(u);
    }
}

// ============================================================================
// Kernel 2: pipelined tf32 mma.sync GEMM (support = adj @ x_proj)
//           + fused logmap + dense(kernel) + bias epilogue
// CTA tile m64 x n64, grid 256, TWO CTAs per SM (independent barrier domains
// -> 4 warps/SMSP latency hiding). 8 warps: wm2 x wn2 x wk2, warp m32 n32 k32.
// KC=64 per stage (2 x 128B SW128 blocks per operand), 3 stages, 96KB smem.
// kernel/bias read from L2 in epilogue (no smem copy).
// ============================================================================
static constexpr int STAGES = 3;
static constexpr int KC     = 64;                // K per stage
static constexpr int ITERS  = N_ROWS / KC;       // 256

static constexpr int STAGE_BYTES = 32768;        // A 16KB + B 16KB
static constexpr int A_OFF       = 0;            // two 8KB half-K blocks
static constexpr int B_OFF       = 16384;        // two 8KB half-K blocks
static constexpr int SMEM_TOTAL  = STAGES * STAGE_BYTES;     // 98304
static constexpr int C_STRIDE    = 68;           // floats per row
static constexpr int C_BYTES     = 64 * C_STRIDE * 4;        // 17408
static constexpr int SMEM_C0     = 0;            // wk=0 partials (ring reuse)
static constexpr int SMEM_C1     = C_BYTES;      // wk=1 partials

__global__ __launch_bounds__(256, 2) void hgc_gemm(
    const float* __restrict__ adj,
    const float* __restrict__ ker,
    const float* __restrict__ bias,
    float* __restrict__ out)
{
    extern __shared__ char smem[];
    const uint32_t sb = smem_u32(smem);
    const int tid  = threadIdx.x;
    const int lane = tid & 31;
    const int wid  = tid >> 5;
    const int wn   = wid & 1;       // 2 warps along N (32 cols each)
    const int wm   = (wid >> 1) & 1;// 2 warps along M (32 rows each)
    const int wk   = wid >> 2;      // 2 warps along K (32 of KC=64 each)
    const int m0   = blockIdx.x * 64;

    // ---- cp.async mapping: 2048 16B chunks / 256 thr = 8 each.
    // Thread handles A rows r0,r0+16,r0+32,r0+48 (j=0..3) then B likewise.
    // SW128 offsets stride linearly by 2048 since row&7 is invariant mod 16.
    const int r0 = tid >> 4, cc = tid & 15;
    const char* gpA = (const char*)(adj + (size_t)(m0 + r0) * N_ROWS) + cc * 16;
    const char* gpB = (const char*)(g_xT + (size_t)r0 * N_ROWS) + cc * 16;
    const uint32_t soA = A_OFF + (cc >> 3) * 8192 + SW128(r0 * 128 + (cc & 7) * 16);
    const uint32_t soB = B_OFF + (cc >> 3) * 8192 + SW128(r0 * 128 + (cc & 7) * 16);
    const size_t GSTR = (size_t)16 * N_ROWS * 4;   // 16 rows in gmem

    // ---- ldmatrix swizzled offsets (per lane, k8 0..3 within this warp's half)
    const int rr = lane & 7, mi = lane >> 3;
    uint32_t aOff[2][4], bOff[2][4];
    {
        const int hA = wk * 8192, hB = wk * 8192;
        const int aKh = (mi >> 1) * 16, bKh = (mi & 1) * 16;
#pragma unroll
        for (int k8 = 0; k8 < 4; k8++) {
            const int kin = k8 * 32;
#pragma unroll
            for (int mt = 0; mt < 2; mt++) {
                const int ar = wm * 32 + mt * 16 + (mi & 1) * 8 + rr;
                aOff[mt][k8] = A_OFF + hA + SW128(ar * 128 + kin + aKh);
            }
#pragma unroll
            for (int g = 0; g < 2; g++) {
                const int bn = wn * 32 + g * 16 + (mi >> 1) * 8 + rr;
                bOff[g][k8] = B_OFF + hB + SW128(bn * 128 + kin + bKh);
            }
        }
    }

    float acc[2][4][4];
#pragma unroll
    for (int mt = 0; mt < 2; mt++)
#pragma unroll
        for (int nt = 0; nt < 4; nt++)
#pragma unroll
            for (int q = 0; q < 4; q++) acc[mt][nt][q] = 0.0f;

    // ---- prologue: fill stages 0..1
#pragma unroll 1
    for (int s = 0; s < STAGES - 1; s++) {
        const uint32_t stb = sb + s * STAGE_BYTES;
        const size_t goff = (size_t)s * 256;
#pragma unroll
        for (int j = 0; j < 4; j++) {
            cp_async16(stb + soA + j * 2048, gpA + j * GSTR + goff);
            cp_async16(stb + soB + j * 2048, gpB + j * GSTR + goff);
        }
        CP_COMMIT();
    }

    // ---- main loop (256 iterations)
#pragma unroll 1
    for (int i = 0; i < ITERS; i++) {
        cp_wait<STAGES - 2>();
        __syncthreads();

        const int nx = i + STAGES - 1;
        if (nx < ITERS) {
            const uint32_t stb = sb + (nx % STAGES) * STAGE_BYTES;
            const size_t goff = (size_t)nx * 256;
#pragma unroll
            for (int j = 0; j < 4; j++) {
                cp_async16(stb + soA + j * 2048, gpA + j * GSTR + goff);
                cp_async16(stb + soB + j * 2048, gpB + j * GSTR + goff);
            }
        }
        CP_COMMIT();

        const uint32_t st = sb + (i % STAGES) * STAGE_BYTES;

        // software pipeline over 4 k8 steps, double-buffered fragments
        uint32_t a[2][2][4], b[2][2][4];
        ldsm_x4(a[0][0], st + aOff[0][0]);
        ldsm_x4(a[0][1], st + aOff[1][0]);
        ldsm_x4(b[0][0], st + bOff[0][0]);
        ldsm_x4(b[0][1], st + bOff[1][0]);
#pragma unroll
        for (int k8 = 0; k8 < 4; k8++) {
            const int cur = k8 & 1, nxt = cur ^ 1;
            if (k8 < 3) {
                ldsm_x4(a[nxt][0], st + aOff[0][k8 + 1]);
                ldsm_x4(a[nxt][1], st + aOff[1][k8 + 1]);
                ldsm_x4(b[nxt][0], st + bOff[0][k8 + 1]);
                ldsm_x4(b[nxt][1], st + bOff[1][k8 + 1]);
            }
            uint32_t ar2[2][4];
#pragma unroll
            for (int mt = 0; mt < 2; mt++)
#pragma unroll
                for (int q = 0; q < 4; q++) ar2[mt][q] = cvt_rna_tf32(a[cur][mt][q]);
#pragma unroll
            for (int mt = 0; mt < 2; mt++)
#pragma unroll
                for (int nt = 0; nt < 4; nt++)
                    mma_tf32(acc[mt][nt], ar2[mt], b[cur][nt >> 1][(nt & 1) * 2],
                             b[cur][nt >> 1][(nt & 1) * 2 + 1]);
        }
    }
    __syncthreads();  // all compute + all real cp.async consumed; reuse ring

    // ---- spill partial accumulators: wk=0 -> C0, wk=1 -> C1
    float* Csm = (float*)(smem + (wk ? SMEM_C1 : SMEM_C0));
#pragma unroll
    for (int mt = 0; mt < 2; mt++) {
        const int R0 = wm * 32 + mt * 16 + (lane >> 2);
#pragma unroll
        for (int nt = 0; nt < 4; nt++) {
            const int C0 = wn * 32 + nt * 8 + (lane & 3) * 2;
            Csm[R0 * C_STRIDE + C0]           = acc[mt][nt][0];
            Csm[R0 * C_STRIDE + C0 + 1]       = acc[mt][nt][1];
            Csm[(R0 + 8) * C_STRIDE + C0]     = acc[mt][nt][2];
            Csm[(R0 + 8) * C_STRIDE + C0 + 1] = acc[mt][nt][3];
        }
    }
    __syncthreads();

    // ---- fused epilogue: k-reduce + logmap + dense + bias (1 thread per row)
    if (tid < 64) {
        float y[64];
        const float4* c0 = (const float4*)((float*)(smem + SMEM_C0) + tid * C_STRIDE);
        const float4* c1 = (const float4*)((float*)(smem + SMEM_C1) + tid * C_STRIDE);
#pragma unroll
        for (int j = 0; j < 16; j++) {
            float4 p = c0[j], q = c1[j];
            ((float4*)y)[j] = make_float4(p.x + q.x, p.y + q.y, p.z + q.z, p.w + q.w);
        }

        float s2 = 0.0f;
#pragma unroll
        for (int j = 0; j < 64; j++) s2 += y[j] * y[j];
        float nrm = sqrtf(s2);
        float nc = fminf(nrm, 0.999f);
        float sc = atanhf(nc) / (nc + 1e-8f);
#pragma unroll
        for (int j = 0; j < 64; j++) y[j] *= sc;

        // kernel/bias straight from L2/L1 (16KB, broadcast across lanes)
        const float4* kf = (const float4*)ker;     // [k][u], 16 float4 per k
        const float4* bv = (const float4*)bias;
        float4* outv = (float4*)(out + (size_t)(m0 + tid) * U_DIM);
#pragma unroll 1
        for (int u0 = 0; u0 < 16; u0++) {
            float4 a4 = __ldg(bv + u0);
#pragma unroll
            for (int k = 0; k < 64; k++) {
                float4 kv = __ldg(kf + k * 16 + u0);
                a4.x += y[k] * kv.x; a4.y += y[k] * kv.y;
                a4.z += y[k] * kv.z; a4.w += y[k] * kv.w;
            }
            outv[u0] = a4;
        }
    }
}

// ============================================================================
// Launch
// ============================================================================
extern "C" void kernel_launch(void* const* d_in, const int* in_sizes, int n_in,
                              void* d_out, int out_size) {
    const float *x = nullptr, *adj = nullptr, *ker = nullptr, *bias = nullptr;
    for (int i = 0; i < n_in; i++) {
        long sz = in_sizes[i];
        if (sz == (long)N_ROWS * N_ROWS)      adj  = (const float*)d_in[i];
        else if (sz == (long)N_ROWS * F_DIM)  x    = (const float*)d_in[i];
        else if (sz == (long)F_DIM * U_DIM)   ker  = (const float*)d_in[i];
        else if (sz == (long)U_DIM)           bias = (const float*)d_in[i];
    }
    float* out = (float*)d_out;

    cudaFuncSetAttribute(hgc_gemm, cudaFuncAttributeMaxDynamicSharedMemorySize, SMEM_TOTAL);

    expmap_transpose<<<N_ROWS / 64, 256>>>(x);
    hgc_gemm<<<N_ROWS / 64, 256, SMEM_TOTAL>>>(adj, ker, bias, out);
}